// round 1
// baseline (speedup 1.0000x reference)
#include <cuda_runtime.h>
#include <math.h>

#define BD    4
#define NSEQ  1024
#define DM    256
#define NH    8
#define HD    32
#define DFFN  1024
#define MROWS (BD * NSEQ)   // 4096

// ---------------- static scratch (no allocations allowed) ----------------
__device__ float g_qkin[MROWS * DM];        // embed + query_pos
__device__ float g_qkout[MROWS * 2 * DM];   // [4096, 512]: q | k
__device__ float g_v[MROWS * DM];           // [4096, 256]
__device__ float g_tau[BD * NH * NSEQ];     // [B, H, N]
__device__ float g_ctx[MROWS * DM];
__device__ float g_y[MROWS * DM];           // pre-LN tmp
__device__ float g_x[MROWS * DM];           // post-LN1
__device__ float g_h[MROWS * DFFN];         // FFN hidden

// ---------------- elementwise: qk = embed + query_pos ----------------
__global__ void add_pos_kernel(const float4* __restrict__ a,
                               const float4* __restrict__ b,
                               float4* __restrict__ o)
{
    int i = blockIdx.x * blockDim.x + threadIdx.x;
    float4 x = a[i], y = b[i];
    o[i] = make_float4(x.x + y.x, x.y + y.y, x.z + y.z, x.w + y.w);
}

// ---------------- tau[b,h,n] = embed[b,n,:] . tau_w[h,:] + tau_b[h] ----------------
__global__ void tau_kernel(const float* __restrict__ embed,
                           const float* __restrict__ tw,
                           const float* __restrict__ tb,
                           float* __restrict__ tau)
{
    int warp_id = (blockIdx.x * blockDim.x + threadIdx.x) >> 5;  // 0..4095
    int lane = threadIdx.x & 31;
    const float* er = embed + (size_t)warp_id * DM;
    float ph[NH];
    #pragma unroll
    for (int h = 0; h < NH; h++) ph[h] = 0.f;
    #pragma unroll
    for (int t = 0; t < 8; t++) {
        int d = lane + t * 32;
        float e = er[d];
        #pragma unroll
        for (int h = 0; h < NH; h++) ph[h] += e * tw[h * DM + d];
    }
    #pragma unroll
    for (int h = 0; h < NH; h++) {
        float v = ph[h];
        #pragma unroll
        for (int o = 16; o > 0; o >>= 1) v += __shfl_xor_sync(0xffffffffu, v, o);
        if (lane == 0) {
            int b = warp_id >> 10, n = warp_id & 1023;
            tau[((size_t)b * NH + h) * NSEQ + n] = v + tb[h];
        }
    }
}

// ---------------- tiled SGEMM: C[M,N] = A[M,K] @ W[N,K]^T + bias (+relu)(+resid) ----------------
// BM=BN=64, BK=16, 256 threads, 4x4 microtile per thread.
__global__ __launch_bounds__(256)
void sgemm_kernel(const float* __restrict__ A, const float* __restrict__ W,
                  const float* __restrict__ bias, const float* __restrict__ resid,
                  float* __restrict__ C, int M, int N, int K, int doRelu)
{
    __shared__ float As[16][68];
    __shared__ float Bs[16][68];
    int tid = threadIdx.x;
    int m0 = blockIdx.y * 64, n0 = blockIdx.x * 64;
    int tr = tid >> 4, tc = tid & 15;            // 16x16 thread grid
    int lm = tid >> 2;                           // 0..63
    int lk = (tid & 3) * 4;                      // 0,4,8,12

    float acc[4][4];
    #pragma unroll
    for (int i = 0; i < 4; i++)
        #pragma unroll
        for (int j = 0; j < 4; j++) acc[i][j] = 0.f;

    const float* Aptr = A + (size_t)(m0 + lm) * K + lk;
    const float* Wptr = W + (size_t)(n0 + lm) * K + lk;

    for (int kt = 0; kt < K; kt += 16) {
        float4 a4 = *(const float4*)(Aptr + kt);
        float4 b4 = *(const float4*)(Wptr + kt);
        __syncthreads();
        As[lk + 0][lm] = a4.x; As[lk + 1][lm] = a4.y;
        As[lk + 2][lm] = a4.z; As[lk + 3][lm] = a4.w;
        Bs[lk + 0][lm] = b4.x; Bs[lk + 1][lm] = b4.y;
        Bs[lk + 2][lm] = b4.z; Bs[lk + 3][lm] = b4.w;
        __syncthreads();
        #pragma unroll
        for (int k = 0; k < 16; k++) {
            float4 av = *(const float4*)&As[k][tr * 4];
            float4 bv = *(const float4*)&Bs[k][tc * 4];
            float a[4] = {av.x, av.y, av.z, av.w};
            float bb[4] = {bv.x, bv.y, bv.z, bv.w};
            #pragma unroll
            for (int i = 0; i < 4; i++)
                #pragma unroll
                for (int j = 0; j < 4; j++) acc[i][j] += a[i] * bb[j];
        }
    }

    int col = n0 + tc * 4;
    float bx = bias[col + 0], by = bias[col + 1], bz = bias[col + 2], bw = bias[col + 3];
    #pragma unroll
    for (int i = 0; i < 4; i++) {
        int row = m0 + tr * 4 + i;
        float4 o;
        o.x = acc[i][0] + bx; o.y = acc[i][1] + by;
        o.z = acc[i][2] + bz; o.w = acc[i][3] + bw;
        if (doRelu) {
            o.x = fmaxf(o.x, 0.f); o.y = fmaxf(o.y, 0.f);
            o.z = fmaxf(o.z, 0.f); o.w = fmaxf(o.w, 0.f);
        }
        if (resid) {
            float4 rr = *(const float4*)(resid + (size_t)row * N + col);
            o.x += rr.x; o.y += rr.y; o.z += rr.z; o.w += rr.w;
        }
        *(float4*)(C + (size_t)row * N + col) = o;
    }
}

// ---------------- flash attention with bias = dist * tau ----------------
// Block: 64 query rows x one head. 256 threads = 64 rows x 4 sub-threads.
__global__ __launch_bounds__(256)
void attn_kernel(const float* __restrict__ qk, const float* __restrict__ vbuf,
                 const float* __restrict__ dist, const float* __restrict__ tau,
                 float* __restrict__ ctx)
{
    __shared__ float ks[64][36];
    __shared__ float vs[64][36];
    __shared__ float ps[64][65];

    int b = blockIdx.z, h = blockIdx.y;
    int i0 = blockIdx.x * 64;
    int tid = threadIdx.x;
    int r = tid >> 2, sub = tid & 3;
    int rowg = b * NSEQ + i0 + r;

    // q row -> registers (4x redundant across sub-threads; broadcast loads)
    float qreg[32];
    const float4* q4 = (const float4*)(qk + (size_t)rowg * 512 + h * 32);
    #pragma unroll
    for (int d4 = 0; d4 < 8; d4++) {
        float4 t = q4[d4];
        qreg[d4 * 4 + 0] = t.x; qreg[d4 * 4 + 1] = t.y;
        qreg[d4 * 4 + 2] = t.z; qreg[d4 * 4 + 3] = t.w;
    }
    float tau_r = tau[((size_t)b * NH + h) * NSEQ + i0 + r];
    const float inv_sqrt = 0.17677669529663687f;  // 1/sqrt(32)
    const float* drow = dist + ((size_t)b * NSEQ + i0 + r) * NSEQ + sub * 16;

    float acc[8];
    #pragma unroll
    for (int d = 0; d < 8; d++) acc[d] = 0.f;
    float mrow = -1e30f, lrow = 0.f;

    for (int j0 = 0; j0 < NSEQ; j0 += 64) {
        __syncthreads();
        {   // load K/V tile: each thread 8 floats of one row
            int d0 = sub * 8;
            const float4* kk = (const float4*)(qk + (size_t)(b * NSEQ + j0 + r) * 512 + 256 + h * 32 + d0);
            float4 ka = kk[0], kb = kk[1];
            *(float4*)&ks[r][d0] = ka; *(float4*)&ks[r][d0 + 4] = kb;
            const float4* vv = (const float4*)(vbuf + (size_t)(b * NSEQ + j0 + r) * 256 + h * 32 + d0);
            float4 va = vv[0], vb = vv[1];
            *(float4*)&vs[r][d0] = va; *(float4*)&vs[r][d0 + 4] = vb;
        }
        float dreg[16];
        #pragma unroll
        for (int u4 = 0; u4 < 4; u4++) {
            float4 dd = *(const float4*)(drow + j0 + u4 * 4);
            dreg[u4 * 4 + 0] = dd.x; dreg[u4 * 4 + 1] = dd.y;
            dreg[u4 * 4 + 2] = dd.z; dreg[u4 * 4 + 3] = dd.w;
        }
        __syncthreads();

        // scores for this thread's 16 columns
        float s[16];
        #pragma unroll
        for (int u = 0; u < 16; u++) {
            int j = sub * 16 + u;
            float sv = 0.f;
            #pragma unroll
            for (int d4 = 0; d4 < 8; d4++) {
                float4 kv = *(const float4*)&ks[j][d4 * 4];
                sv += qreg[d4 * 4 + 0] * kv.x + qreg[d4 * 4 + 1] * kv.y
                    + qreg[d4 * 4 + 2] * kv.z + qreg[d4 * 4 + 3] * kv.w;
            }
            s[u] = sv * inv_sqrt + dreg[u] * tau_r;
        }

        float tmax = s[0];
        #pragma unroll
        for (int u = 1; u < 16; u++) tmax = fmaxf(tmax, s[u]);
        tmax = fmaxf(tmax, __shfl_xor_sync(0xffffffffu, tmax, 1));
        tmax = fmaxf(tmax, __shfl_xor_sync(0xffffffffu, tmax, 2));

        float mnew = fmaxf(mrow, tmax);
        float corr = __expf(mrow - mnew);
        float psum = 0.f;
        #pragma unroll
        for (int u = 0; u < 16; u++) {
            float p = __expf(s[u] - mnew);
            s[u] = p;
            psum += p;
        }
        psum += __shfl_xor_sync(0xffffffffu, psum, 1);
        psum += __shfl_xor_sync(0xffffffffu, psum, 2);
        lrow = lrow * corr + psum;
        mrow = mnew;
        #pragma unroll
        for (int d = 0; d < 8; d++) acc[d] *= corr;
        #pragma unroll
        for (int u = 0; u < 16; u++) ps[r][sub * 16 + u] = s[u];
        __syncthreads();

        // acc += P @ V  (thread owns dims sub*8 .. sub*8+7)
        int d0 = sub * 8;
        #pragma unroll 8
        for (int j = 0; j < 64; j++) {
            float pj = ps[r][j];
            float4 va = *(const float4*)&vs[j][d0];
            float4 vb = *(const float4*)&vs[j][d0 + 4];
            acc[0] += pj * va.x; acc[1] += pj * va.y;
            acc[2] += pj * va.z; acc[3] += pj * va.w;
            acc[4] += pj * vb.x; acc[5] += pj * vb.y;
            acc[6] += pj * vb.z; acc[7] += pj * vb.w;
        }
    }

    float invl = 1.f / lrow;
    float4 o1 = make_float4(acc[0] * invl, acc[1] * invl, acc[2] * invl, acc[3] * invl);
    float4 o2 = make_float4(acc[4] * invl, acc[5] * invl, acc[6] * invl, acc[7] * invl);
    float* op = ctx + (size_t)rowg * 256 + h * 32 + sub * 8;
    *(float4*)op = o1;
    *(float4*)(op + 4) = o2;
}

// ---------------- row LayerNorm over 256 features ----------------
__global__ void ln_kernel(const float* __restrict__ in, const float* __restrict__ g,
                          const float* __restrict__ bt, float* __restrict__ out)
{
    int row = blockIdx.x, t = threadIdx.x;
    float v = in[(size_t)row * DM + t];
    float s = v, s2 = v * v;
    #pragma unroll
    for (int o = 16; o > 0; o >>= 1) {
        s  += __shfl_xor_sync(0xffffffffu, s, o);
        s2 += __shfl_xor_sync(0xffffffffu, s2, o);
    }
    __shared__ float rs[8], rs2[8];
    __shared__ float mu_s, rstd_s;
    int w = t >> 5, lane = t & 31;
    if (lane == 0) { rs[w] = s; rs2[w] = s2; }
    __syncthreads();
    if (t == 0) {
        float a = 0.f, b2 = 0.f;
        #pragma unroll
        for (int i = 0; i < 8; i++) { a += rs[i]; b2 += rs2[i]; }
        float mu = a * (1.f / 256.f);
        float var = b2 * (1.f / 256.f) - mu * mu;
        mu_s = mu;
        rstd_s = rsqrtf(var + 1e-5f);
    }
    __syncthreads();
    out[(size_t)row * DM + t] = (v - mu_s) * rstd_s * g[t] + bt[t];
}

// ---------------- launch ----------------
static float* sym_addr(const void* sym)
{
    void* p = nullptr;
    cudaGetSymbolAddress(&p, sym);
    return (float*)p;
}

extern "C" void kernel_launch(void* const* d_in, const int* in_sizes, int n_in,
                              void* d_out, int out_size)
{
    const float* embed = (const float*)d_in[0];
    const float* dist  = (const float*)d_in[2];
    const float* qpos  = (const float*)d_in[3];
    const float* inw   = (const float*)d_in[4];
    const float* inb   = (const float*)d_in[5];
    const float* outw  = (const float*)d_in[6];
    const float* outb  = (const float*)d_in[7];
    const float* tauw  = (const float*)d_in[8];
    const float* taub  = (const float*)d_in[9];
    const float* w1    = (const float*)d_in[10];
    const float* b1    = (const float*)d_in[11];
    const float* w2    = (const float*)d_in[12];
    const float* b2    = (const float*)d_in[13];
    const float* g1    = (const float*)d_in[14];
    const float* be1   = (const float*)d_in[15];
    const float* g2    = (const float*)d_in[16];
    const float* be2   = (const float*)d_in[17];
    float* out = (float*)d_out;

    float* qkin  = sym_addr(g_qkin);
    float* qkout = sym_addr(g_qkout);
    float* v     = sym_addr(g_v);
    float* tau   = sym_addr(g_tau);
    float* ctx   = sym_addr(g_ctx);
    float* y     = sym_addr(g_y);
    float* x     = sym_addr(g_x);
    float* hbuf  = sym_addr(g_h);

    // 1) qk = embed + query_pos
    add_pos_kernel<<<(MROWS * DM / 4) / 256, 256>>>(
        (const float4*)embed, (const float4*)qpos, (float4*)qkin);

    // 2) tau (B,H,N)
    tau_kernel<<<512, 256>>>(embed, tauw, taub, tau);

    // 3) q|k projection: [4096,256] @ [512,256]^T
    sgemm_kernel<<<dim3(512 / 64, MROWS / 64), 256>>>(
        qkin, inw, inb, nullptr, qkout, MROWS, 512, DM, 0);

    // 4) v projection: embed @ wv^T
    sgemm_kernel<<<dim3(DM / 64, MROWS / 64), 256>>>(
        embed, inw + 512 * DM, inb + 512, nullptr, v, MROWS, DM, DM, 0);

    // 5) attention
    attn_kernel<<<dim3(NSEQ / 64, NH, BD), 256>>>(qkout, v, dist, tau, ctx);

    // 6) out projection + residual(embed)
    sgemm_kernel<<<dim3(DM / 64, MROWS / 64), 256>>>(
        ctx, outw, outb, embed, y, MROWS, DM, DM, 0);

    // 7) LN1
    ln_kernel<<<MROWS, 256>>>(y, g1, be1, x);

    // 8) FFN1 + ReLU
    sgemm_kernel<<<dim3(DFFN / 64, MROWS / 64), 256>>>(
        x, w1, b1, nullptr, hbuf, MROWS, DFFN, DM, 1);

    // 9) FFN2 + residual(x)
    sgemm_kernel<<<dim3(DM / 64, MROWS / 64), 256>>>(
        hbuf, w2, b2, x, y, MROWS, DM, DFFN, 0);

    // 10) LN2 -> out
    ln_kernel<<<MROWS, 256>>>(y, g2, be2, out);
}

// round 2
// speedup vs baseline: 4.6171x; 4.6171x over previous
#include <cuda_runtime.h>
#include <math.h>

#define BD    4
#define NSEQ  1024
#define DM    256
#define NH    8
#define HD    32
#define DFFN  1024
#define MROWS (BD * NSEQ)   // 4096

// ---------------- static scratch ----------------
__device__ float g_qkin[MROWS * DM];        // embed + query_pos
__device__ float g_qkout[MROWS * 2 * DM];   // [4096, 512]: q | k
__device__ float g_v[MROWS * DM];
__device__ float g_tau[BD * NH * NSEQ];     // [B, H, N]
__device__ float g_ctx[MROWS * DM];
__device__ float g_y[MROWS * DM];
__device__ float g_x[MROWS * DM];
__device__ float g_h[MROWS * DFFN];

// ---------------- tf32 helpers ----------------
__device__ __forceinline__ unsigned f2tf(float f)
{
    unsigned u;
    asm("cvt.rna.tf32.f32 %0, %1;" : "=r"(u) : "f"(f));
    return u;
}
__device__ __forceinline__ uint4 cvt4(float4 f)
{
    uint4 u;
    u.x = f2tf(f.x); u.y = f2tf(f.y); u.z = f2tf(f.z); u.w = f2tf(f.w);
    return u;
}

#define MMA_TF32(d, a, b0, b1)                                              \
    asm volatile("mma.sync.aligned.m16n8k8.row.col.f32.tf32.tf32.f32 "      \
                 "{%0,%1,%2,%3}, {%4,%5,%6,%7}, {%8,%9}, {%0,%1,%2,%3};"    \
                 : "+f"((d)[0]), "+f"((d)[1]), "+f"((d)[2]), "+f"((d)[3])   \
                 : "r"((a)[0]), "r"((a)[1]), "r"((a)[2]), "r"((a)[3]),      \
                   "r"(b0), "r"(b1))

// ---------------- elementwise: qk = embed + query_pos ----------------
__global__ void add_pos_kernel(const float4* __restrict__ a,
                               const float4* __restrict__ b,
                               float4* __restrict__ o)
{
    int i = blockIdx.x * blockDim.x + threadIdx.x;
    float4 x = a[i], y = b[i];
    o[i] = make_float4(x.x + y.x, x.y + y.y, x.z + y.z, x.w + y.w);
}

// ---------------- tau[b,h,n] = embed[b,n,:] . tau_w[h,:] + tau_b[h] ----------------
__global__ void tau_kernel(const float* __restrict__ embed,
                           const float* __restrict__ tw,
                           const float* __restrict__ tb,
                           float* __restrict__ tau)
{
    int warp_id = (blockIdx.x * blockDim.x + threadIdx.x) >> 5;
    int lane = threadIdx.x & 31;
    const float* er = embed + (size_t)warp_id * DM;
    float ph[NH];
    #pragma unroll
    for (int h = 0; h < NH; h++) ph[h] = 0.f;
    #pragma unroll
    for (int t = 0; t < 8; t++) {
        int d = lane + t * 32;
        float e = er[d];
        #pragma unroll
        for (int h = 0; h < NH; h++) ph[h] += e * tw[h * DM + d];
    }
    #pragma unroll
    for (int h = 0; h < NH; h++) {
        float v = ph[h];
        #pragma unroll
        for (int o = 16; o > 0; o >>= 1) v += __shfl_xor_sync(0xffffffffu, v, o);
        if (lane == 0) {
            int b = warp_id >> 10, n = warp_id & 1023;
            tau[((size_t)b * NH + h) * NSEQ + n] = v + tb[h];
        }
    }
}

// ---------------- tf32 tensor-core GEMM ----------------
// C[M,N] = A[M,K] @ W[N,K]^T + bias (+relu) (+resid)
// BM=128, BN=64, BK=32, 256 threads (8 warps, 4x2 over MxN), 4x4 mma tiles/warp.
__global__ __launch_bounds__(256)
void sgemm_tc(const float* __restrict__ A, const float* __restrict__ W,
              const float* __restrict__ bias, const float* __restrict__ resid,
              float* __restrict__ C, int M, int N, int K, int doRelu)
{
    __shared__ __align__(16) unsigned As[128 * 36];
    __shared__ __align__(16) unsigned Bs[64 * 36];

    int tid = threadIdx.x, lane = tid & 31, wid = tid >> 5;
    int m0 = blockIdx.y * 128, n0 = blockIdx.x * 64;
    int ldr = tid >> 3, ldc = (tid & 7) * 4;

    const float* Ag = A + (size_t)(m0 + ldr) * K + ldc;
    const float* Bg = W + (size_t)(n0 + ldr) * K + ldc;

    float4 apf[4], bpf[2];
    #pragma unroll
    for (int i = 0; i < 4; i++) apf[i] = *(const float4*)(Ag + (size_t)(32 * i) * K);
    #pragma unroll
    for (int i = 0; i < 2; i++) bpf[i] = *(const float4*)(Bg + (size_t)(32 * i) * K);

    int wm = (wid & 3) * 32, wn = (wid >> 2) * 32;
    int gr = lane >> 2, gq = lane & 3;

    float acc[2][4][4];
    #pragma unroll
    for (int mi = 0; mi < 2; mi++)
        #pragma unroll
        for (int ni = 0; ni < 4; ni++)
            #pragma unroll
            for (int k = 0; k < 4; k++) acc[mi][ni][k] = 0.f;

    for (int kt = 0; kt < K; kt += 32) {
        __syncthreads();
        #pragma unroll
        for (int i = 0; i < 4; i++)
            *(uint4*)&As[(ldr + 32 * i) * 36 + ldc] = cvt4(apf[i]);
        #pragma unroll
        for (int i = 0; i < 2; i++)
            *(uint4*)&Bs[(ldr + 32 * i) * 36 + ldc] = cvt4(bpf[i]);
        __syncthreads();
        if (kt + 32 < K) {
            #pragma unroll
            for (int i = 0; i < 4; i++)
                apf[i] = *(const float4*)(Ag + (size_t)(32 * i) * K + kt + 32);
            #pragma unroll
            for (int i = 0; i < 2; i++)
                bpf[i] = *(const float4*)(Bg + (size_t)(32 * i) * K + kt + 32);
        }
        #pragma unroll
        for (int k0 = 0; k0 < 32; k0 += 8) {
            unsigned af[2][4], bf[4][2];
            #pragma unroll
            for (int mi = 0; mi < 2; mi++) {
                int r = wm + mi * 16 + gr, c = k0 + gq;
                af[mi][0] = As[r * 36 + c];
                af[mi][1] = As[(r + 8) * 36 + c];
                af[mi][2] = As[r * 36 + c + 4];
                af[mi][3] = As[(r + 8) * 36 + c + 4];
            }
            #pragma unroll
            for (int ni = 0; ni < 4; ni++) {
                int cc = wn + ni * 8 + gr;
                bf[ni][0] = Bs[cc * 36 + k0 + gq];
                bf[ni][1] = Bs[cc * 36 + k0 + 4 + gq];
            }
            #pragma unroll
            for (int mi = 0; mi < 2; mi++)
                #pragma unroll
                for (int ni = 0; ni < 4; ni++)
                    MMA_TF32(acc[mi][ni], af[mi], bf[ni][0], bf[ni][1]);
        }
    }

    // epilogue
    #pragma unroll
    for (int mi = 0; mi < 2; mi++) {
        #pragma unroll
        for (int ni = 0; ni < 4; ni++) {
            int r = m0 + wm + mi * 16 + gr;
            int c = n0 + wn + ni * 8 + 2 * gq;
            float2 bb = *(const float2*)(bias + c);
            float v0 = acc[mi][ni][0] + bb.x, v1 = acc[mi][ni][1] + bb.y;
            float v2 = acc[mi][ni][2] + bb.x, v3 = acc[mi][ni][3] + bb.y;
            if (doRelu) {
                v0 = fmaxf(v0, 0.f); v1 = fmaxf(v1, 0.f);
                v2 = fmaxf(v2, 0.f); v3 = fmaxf(v3, 0.f);
            }
            if (resid) {
                float2 r0v = *(const float2*)(resid + (size_t)r * N + c);
                float2 r1v = *(const float2*)(resid + (size_t)(r + 8) * N + c);
                v0 += r0v.x; v1 += r0v.y; v2 += r1v.x; v3 += r1v.y;
            }
            *(float2*)(C + (size_t)r * N + c) = make_float2(v0, v1);
            *(float2*)(C + (size_t)(r + 8) * N + c) = make_float2(v2, v3);
        }
    }
}

// ---------------- tf32 tensor-core flash attention ----------------
// Block: 64 q-rows x 1 head, 128 threads (4 warps, 16 rows each).
__global__ __launch_bounds__(128)
void attn_tc(const float* __restrict__ qk, const float* __restrict__ vbuf,
             const float* __restrict__ dist, const float* __restrict__ tau,
             float* __restrict__ ctx)
{
    __shared__ __align__(16) unsigned Qs[64 * 36];
    __shared__ __align__(16) unsigned Ks[64 * 36];
    __shared__ __align__(16) unsigned Vs[64 * 36];
    __shared__ __align__(16) unsigned Ps[64 * 68];

    int b = blockIdx.z, h = blockIdx.y, i0 = blockIdx.x * 64;
    int tid = threadIdx.x, lane = tid & 31, w = tid >> 5;
    int gr = lane >> 2, gq = lane & 3;
    int lr0 = w * 16 + gr;

    // load Q tile (tf32)
    {
        int r0 = tid >> 3, c = (tid & 7) * 4;
        #pragma unroll
        for (int i = 0; i < 4; i++) {
            int row = r0 + 16 * i;
            float4 q = *(const float4*)(qk + (size_t)(b * NSEQ + i0 + row) * 512 + h * 32 + c);
            *(uint4*)&Qs[row * 36 + c] = cvt4(q);
        }
    }

    float tau0 = tau[((size_t)b * NH + h) * NSEQ + i0 + lr0];
    float tau1 = tau[((size_t)b * NH + h) * NSEQ + i0 + lr0 + 8];
    const float* d0p = dist + ((size_t)b * NSEQ + i0 + lr0) * NSEQ;
    const float* d1p = d0p + (size_t)8 * NSEQ;

    float m0 = -1e30f, m1 = -1e30f, l0 = 0.f, l1 = 0.f;
    float o[4][4];
    #pragma unroll
    for (int ni = 0; ni < 4; ni++)
        #pragma unroll
        for (int k = 0; k < 4; k++) o[ni][k] = 0.f;

    const float sc = 0.17677669529663687f;  // 1/sqrt(32)

    for (int j0 = 0; j0 < NSEQ; j0 += 64) {
        __syncthreads();
        {   // load K/V tiles (tf32)
            int r0 = tid >> 3, c = (tid & 7) * 4;
            #pragma unroll
            for (int i = 0; i < 4; i++) {
                int row = r0 + 16 * i;
                float4 kv = *(const float4*)(qk + (size_t)(b * NSEQ + j0 + row) * 512 + 256 + h * 32 + c);
                *(uint4*)&Ks[row * 36 + c] = cvt4(kv);
                float4 vv = *(const float4*)(vbuf + (size_t)(b * NSEQ + j0 + row) * 256 + h * 32 + c);
                *(uint4*)&Vs[row * 36 + c] = cvt4(vv);
            }
        }
        __syncthreads();

        // S = Q @ K^T  (16 rows x 64 cols per warp)
        float s[8][4];
        #pragma unroll
        for (int ni = 0; ni < 8; ni++)
            #pragma unroll
            for (int k = 0; k < 4; k++) s[ni][k] = 0.f;

        #pragma unroll
        for (int k0 = 0; k0 < 32; k0 += 8) {
            unsigned af[4];
            af[0] = Qs[lr0 * 36 + k0 + gq];
            af[1] = Qs[(lr0 + 8) * 36 + k0 + gq];
            af[2] = Qs[lr0 * 36 + k0 + 4 + gq];
            af[3] = Qs[(lr0 + 8) * 36 + k0 + 4 + gq];
            #pragma unroll
            for (int ni = 0; ni < 8; ni++) {
                int jj = ni * 8 + gr;
                unsigned b0 = Ks[jj * 36 + k0 + gq];
                unsigned b1 = Ks[jj * 36 + k0 + 4 + gq];
                MMA_TF32(s[ni], af, b0, b1);
            }
        }

        // bias + online softmax
        float tm0 = -1e30f, tm1 = -1e30f;
        #pragma unroll
        for (int ni = 0; ni < 8; ni++) {
            int jc = j0 + ni * 8 + 2 * gq;
            float2 d01 = *(const float2*)(d0p + jc);
            float2 d23 = *(const float2*)(d1p + jc);
            s[ni][0] = s[ni][0] * sc + d01.x * tau0;
            s[ni][1] = s[ni][1] * sc + d01.y * tau0;
            s[ni][2] = s[ni][2] * sc + d23.x * tau1;
            s[ni][3] = s[ni][3] * sc + d23.y * tau1;
            tm0 = fmaxf(tm0, fmaxf(s[ni][0], s[ni][1]));
            tm1 = fmaxf(tm1, fmaxf(s[ni][2], s[ni][3]));
        }
        tm0 = fmaxf(tm0, __shfl_xor_sync(0xffffffffu, tm0, 1));
        tm0 = fmaxf(tm0, __shfl_xor_sync(0xffffffffu, tm0, 2));
        tm1 = fmaxf(tm1, __shfl_xor_sync(0xffffffffu, tm1, 1));
        tm1 = fmaxf(tm1, __shfl_xor_sync(0xffffffffu, tm1, 2));

        float mn0 = fmaxf(m0, tm0), mn1 = fmaxf(m1, tm1);
        float cor0 = __expf(m0 - mn0), cor1 = __expf(m1 - mn1);
        float ps0 = 0.f, ps1 = 0.f;
        #pragma unroll
        for (int ni = 0; ni < 8; ni++) {
            s[ni][0] = __expf(s[ni][0] - mn0);
            s[ni][1] = __expf(s[ni][1] - mn0);
            s[ni][2] = __expf(s[ni][2] - mn1);
            s[ni][3] = __expf(s[ni][3] - mn1);
            ps0 += s[ni][0] + s[ni][1];
            ps1 += s[ni][2] + s[ni][3];
        }
        ps0 += __shfl_xor_sync(0xffffffffu, ps0, 1);
        ps0 += __shfl_xor_sync(0xffffffffu, ps0, 2);
        ps1 += __shfl_xor_sync(0xffffffffu, ps1, 1);
        ps1 += __shfl_xor_sync(0xffffffffu, ps1, 2);
        l0 = l0 * cor0 + ps0;
        l1 = l1 * cor1 + ps1;
        m0 = mn0; m1 = mn1;

        #pragma unroll
        for (int ni = 0; ni < 4; ni++) {
            o[ni][0] *= cor0; o[ni][1] *= cor0;
            o[ni][2] *= cor1; o[ni][3] *= cor1;
        }

        // stage P (C-layout -> smem, per-warp-private strip)
        #pragma unroll
        for (int ni = 0; ni < 8; ni++) {
            int jc = ni * 8 + 2 * gq;
            Ps[lr0 * 68 + jc]           = f2tf(s[ni][0]);
            Ps[lr0 * 68 + jc + 1]       = f2tf(s[ni][1]);
            Ps[(lr0 + 8) * 68 + jc]     = f2tf(s[ni][2]);
            Ps[(lr0 + 8) * 68 + jc + 1] = f2tf(s[ni][3]);
        }
        __syncwarp();

        // O += P @ V
        #pragma unroll
        for (int k0 = 0; k0 < 64; k0 += 8) {
            unsigned af[4];
            af[0] = Ps[lr0 * 68 + k0 + gq];
            af[1] = Ps[(lr0 + 8) * 68 + k0 + gq];
            af[2] = Ps[lr0 * 68 + k0 + 4 + gq];
            af[3] = Ps[(lr0 + 8) * 68 + k0 + 4 + gq];
            #pragma unroll
            for (int ni = 0; ni < 4; ni++) {
                unsigned b0 = Vs[(k0 + gq) * 36 + ni * 8 + gr];
                unsigned b1 = Vs[(k0 + 4 + gq) * 36 + ni * 8 + gr];
                MMA_TF32(o[ni], af, b0, b1);
            }
        }
    }

    float il0 = 1.f / l0, il1 = 1.f / l1;
    size_t gi0 = (size_t)(b * NSEQ + i0 + lr0) * 256;
    size_t gi1 = gi0 + (size_t)8 * 256;
    #pragma unroll
    for (int ni = 0; ni < 4; ni++) {
        int dcol = h * 32 + ni * 8 + 2 * gq;
        *(float2*)(ctx + gi0 + dcol) = make_float2(o[ni][0] * il0, o[ni][1] * il0);
        *(float2*)(ctx + gi1 + dcol) = make_float2(o[ni][2] * il1, o[ni][3] * il1);
    }
}

// ---------------- row LayerNorm over 256 features ----------------
__global__ void ln_kernel(const float* __restrict__ in, const float* __restrict__ g,
                          const float* __restrict__ bt, float* __restrict__ out)
{
    int row = blockIdx.x, t = threadIdx.x;
    float v = in[(size_t)row * DM + t];
    float s = v, s2 = v * v;
    #pragma unroll
    for (int o = 16; o > 0; o >>= 1) {
        s  += __shfl_xor_sync(0xffffffffu, s, o);
        s2 += __shfl_xor_sync(0xffffffffu, s2, o);
    }
    __shared__ float rs[8], rs2[8];
    __shared__ float mu_s, rstd_s;
    int w = t >> 5, lane = t & 31;
    if (lane == 0) { rs[w] = s; rs2[w] = s2; }
    __syncthreads();
    if (t == 0) {
        float a = 0.f, b2 = 0.f;
        #pragma unroll
        for (int i = 0; i < 8; i++) { a += rs[i]; b2 += rs2[i]; }
        float mu = a * (1.f / 256.f);
        float var = b2 * (1.f / 256.f) - mu * mu;
        mu_s = mu;
        rstd_s = rsqrtf(var + 1e-5f);
    }
    __syncthreads();
    out[(size_t)row * DM + t] = (v - mu_s) * rstd_s * g[t] + bt[t];
}

// ---------------- launch ----------------
static float* sym_addr(const void* sym)
{
    void* p = nullptr;
    cudaGetSymbolAddress(&p, sym);
    return (float*)p;
}

extern "C" void kernel_launch(void* const* d_in, const int* in_sizes, int n_in,
                              void* d_out, int out_size)
{
    const float* embed = (const float*)d_in[0];
    const float* dist  = (const float*)d_in[2];
    const float* qpos  = (const float*)d_in[3];
    const float* inw   = (const float*)d_in[4];
    const float* inb   = (const float*)d_in[5];
    const float* outw  = (const float*)d_in[6];
    const float* outb  = (const float*)d_in[7];
    const float* tauw  = (const float*)d_in[8];
    const float* taub  = (const float*)d_in[9];
    const float* w1    = (const float*)d_in[10];
    const float* b1    = (const float*)d_in[11];
    const float* w2    = (const float*)d_in[12];
    const float* b2    = (const float*)d_in[13];
    const float* g1    = (const float*)d_in[14];
    const float* be1   = (const float*)d_in[15];
    const float* g2    = (const float*)d_in[16];
    const float* be2   = (const float*)d_in[17];
    float* out = (float*)d_out;

    float* qkin  = sym_addr(g_qkin);
    float* qkout = sym_addr(g_qkout);
    float* v     = sym_addr(g_v);
    float* tau   = sym_addr(g_tau);
    float* ctx   = sym_addr(g_ctx);
    float* y     = sym_addr(g_y);
    float* x     = sym_addr(g_x);
    float* hbuf  = sym_addr(g_h);

    // 1) qk = embed + query_pos
    add_pos_kernel<<<(MROWS * DM / 4) / 256, 256>>>(
        (const float4*)embed, (const float4*)qpos, (float4*)qkin);

    // 2) tau (B,H,N)
    tau_kernel<<<512, 256>>>(embed, tauw, taub, tau);

    // 3) q|k projection: [4096,256] @ [512,256]^T
    sgemm_tc<<<dim3(512 / 64, MROWS / 128), 256>>>(
        qkin, inw, inb, nullptr, qkout, MROWS, 512, DM, 0);

    // 4) v projection
    sgemm_tc<<<dim3(DM / 64, MROWS / 128), 256>>>(
        embed, inw + 512 * DM, inb + 512, nullptr, v, MROWS, DM, DM, 0);

    // 5) attention
    attn_tc<<<dim3(NSEQ / 64, NH, BD), 128>>>(qkout, v, dist, tau, ctx);

    // 6) out projection + residual(embed)
    sgemm_tc<<<dim3(DM / 64, MROWS / 128), 256>>>(
        ctx, outw, outb, embed, y, MROWS, DM, DM, 0);

    // 7) LN1
    ln_kernel<<<MROWS, 256>>>(y, g1, be1, x);

    // 8) FFN1 + ReLU
    sgemm_tc<<<dim3(DFFN / 64, MROWS / 128), 256>>>(
        x, w1, b1, nullptr, hbuf, MROWS, DFFN, DM, 1);

    // 9) FFN2 + residual(x)
    sgemm_tc<<<dim3(DM / 64, MROWS / 128), 256>>>(
        hbuf, w2, b2, x, y, MROWS, DM, DFFN, 0);

    // 10) LN2 -> out
    ln_kernel<<<MROWS, 256>>>(y, g2, be2, out);
}

// round 5
// speedup vs baseline: 5.0326x; 1.0900x over previous
#include <cuda_runtime.h>
#include <stdint.h>
#include <math.h>

#define BD    4
#define NSEQ  1024
#define DM    256
#define NH    8
#define HD    32
#define DFFN  1024
#define MROWS (BD * NSEQ)   // 4096
#define NQKV  768

// ---------------- static scratch ----------------
__device__ float g_qkin[MROWS * DM];        // embed + query_pos
__device__ float g_qkv[MROWS * NQKV];       // [4096, 768]: q | k | v
__device__ float g_tau[BD * NH * NSEQ];     // [B, H, N]
__device__ float g_ctx[MROWS * DM];
__device__ float g_y[MROWS * DM];
__device__ float g_x[MROWS * DM];
__device__ float g_h[MROWS * DFFN];

// ---------------- helpers ----------------
__device__ __forceinline__ unsigned f2tf(float f)
{
    unsigned u;
    asm("cvt.rna.tf32.f32 %0, %1;" : "=r"(u) : "f"(f));
    return u;
}

__device__ __forceinline__ void cp16(float* dst, const float* src)
{
    unsigned d = (unsigned)__cvta_generic_to_shared(dst);
    asm volatile("cp.async.cg.shared.global [%0], [%1], 16;" :: "r"(d), "l"(src));
}

#define CP_COMMIT() asm volatile("cp.async.commit_group;")

#define MMA_TF32(d, a, b0, b1)                                              \
    asm volatile("mma.sync.aligned.m16n8k8.row.col.f32.tf32.tf32.f32 "      \
                 "{%0,%1,%2,%3}, {%4,%5,%6,%7}, {%8,%9}, {%0,%1,%2,%3};"    \
                 : "+f"((d)[0]), "+f"((d)[1]), "+f"((d)[2]), "+f"((d)[3])   \
                 : "r"((a)[0]), "r"((a)[1]), "r"((a)[2]), "r"((a)[3]),      \
                   "r"(b0), "r"(b1))

// ---------------- elementwise: qk = embed + query_pos ----------------
__global__ void add_pos_kernel(const float4* __restrict__ a,
                               const float4* __restrict__ b,
                               float4* __restrict__ o)
{
    int i = blockIdx.x * blockDim.x + threadIdx.x;
    float4 x = a[i], y = b[i];
    o[i] = make_float4(x.x + y.x, x.y + y.y, x.z + y.z, x.w + y.w);
}

// ---------------- tau ----------------
__global__ void tau_kernel(const float* __restrict__ embed,
                           const float* __restrict__ tw,
                           const float* __restrict__ tb,
                           float* __restrict__ tau)
{
    int warp_id = (blockIdx.x * blockDim.x + threadIdx.x) >> 5;
    int lane = threadIdx.x & 31;
    const float* er = embed + (size_t)warp_id * DM;
    float ph[NH];
    #pragma unroll
    for (int h = 0; h < NH; h++) ph[h] = 0.f;
    #pragma unroll
    for (int t = 0; t < 8; t++) {
        int d = lane + t * 32;
        float e = er[d];
        #pragma unroll
        for (int h = 0; h < NH; h++) ph[h] += e * tw[h * DM + d];
    }
    #pragma unroll
    for (int h = 0; h < NH; h++) {
        float v = ph[h];
        #pragma unroll
        for (int o = 16; o > 0; o >>= 1) v += __shfl_xor_sync(0xffffffffu, v, o);
        if (lane == 0) {
            int b = warp_id >> 10, n = warp_id & 1023;
            tau[((size_t)b * NH + h) * NSEQ + n] = v + tb[h];
        }
    }
}

// ---------------- async tile loader for GEMM ----------------
template<int BM>
__device__ __forceinline__ void gemm_load(const float* __restrict__ Ag,
                                          const float* __restrict__ Wg,
                                          float* sA, float* sB, int tid, int K)
{
    constexpr int T = BM * 2;
    #pragma unroll
    for (int i = 0; i < (BM * 8) / T; i++) {
        int idx = tid + i * T;
        int row = idx >> 3, c4 = (idx & 7) << 2;
        cp16(sA + row * 36 + c4, Ag + (size_t)row * K + c4);
    }
    #pragma unroll
    for (int i = 0; i < 512 / T; i++) {
        int idx = tid + i * T;
        int row = idx >> 3, c4 = (idx & 7) << 2;
        cp16(sB + row * 36 + c4, Wg + (size_t)row * K + c4);
    }
    CP_COMMIT();
}

// ---------------- tf32 tensor-core GEMM (double-buffered cp.async) ----------------
// C[M,N] = A[M,K] @ W[N,K]^T + bias (+relu)(+resid); BN=64, BK=32.
// BM=128 -> 256 thr (4x2 warps); BM=64 -> 128 thr (2x2 warps).
template<int BM>
__global__ void gemm_tc(const float* __restrict__ A, const float* __restrict__ A2,
                        const float* __restrict__ W, const float* __restrict__ bias,
                        const float* __restrict__ resid, float* __restrict__ C,
                        int M, int N, int K, int doRelu, int nsplit)
{
    extern __shared__ float smem[];
    constexpr int STAGE = (BM + 64) * 36;
    int tid = threadIdx.x, lane = tid & 31, wid = tid >> 5;
    int m0 = blockIdx.y * BM, n0 = blockIdx.x * 64;
    const float* Ause = (n0 >= nsplit) ? A2 : A;
    const float* Abase = Ause + (size_t)m0 * K;
    const float* Wbase = W + (size_t)n0 * K;
    int nk = K >> 5;

    constexpr int WMN = BM / 32;
    int wm = (wid % WMN) * 32, wn = (wid / WMN) * 32;
    int gr = lane >> 2, gq = lane & 3;

    gemm_load<BM>(Abase, Wbase, smem, smem + BM * 36, tid, K);

    float acc[2][4][4];
    #pragma unroll
    for (int mi = 0; mi < 2; mi++)
        #pragma unroll
        for (int ni = 0; ni < 4; ni++)
            #pragma unroll
            for (int k = 0; k < 4; k++) acc[mi][ni][k] = 0.f;

    for (int kt = 0; kt < nk; kt++) {
        float* cur = smem + (kt & 1) * STAGE;
        float* nxt = smem + ((kt + 1) & 1) * STAGE;
        if (kt + 1 < nk) {
            gemm_load<BM>(Abase + (kt + 1) * 32, Wbase + (kt + 1) * 32,
                          nxt, nxt + BM * 36, tid, K);
            asm volatile("cp.async.wait_group 1;");
        } else {
            asm volatile("cp.async.wait_group 0;");
        }
        __syncthreads();
        const float* cA = cur;
        const float* cB = cur + BM * 36;
        #pragma unroll
        for (int k0 = 0; k0 < 32; k0 += 8) {
            unsigned af[2][4], bf[4][2];
            #pragma unroll
            for (int mi = 0; mi < 2; mi++) {
                int r = wm + mi * 16 + gr, c = k0 + gq;
                af[mi][0] = __float_as_uint(cA[r * 36 + c]);
                af[mi][1] = __float_as_uint(cA[(r + 8) * 36 + c]);
                af[mi][2] = __float_as_uint(cA[r * 36 + c + 4]);
                af[mi][3] = __float_as_uint(cA[(r + 8) * 36 + c + 4]);
            }
            #pragma unroll
            for (int ni = 0; ni < 4; ni++) {
                int cc = wn + ni * 8 + gr;
                bf[ni][0] = __float_as_uint(cB[cc * 36 + k0 + gq]);
                bf[ni][1] = __float_as_uint(cB[cc * 36 + k0 + 4 + gq]);
            }
            #pragma unroll
            for (int mi = 0; mi < 2; mi++)
                #pragma unroll
                for (int ni = 0; ni < 4; ni++)
                    MMA_TF32(acc[mi][ni], af[mi], bf[ni][0], bf[ni][1]);
        }
        __syncthreads();
    }

    #pragma unroll
    for (int mi = 0; mi < 2; mi++) {
        #pragma unroll
        for (int ni = 0; ni < 4; ni++) {
            int r = m0 + wm + mi * 16 + gr;
            int c = n0 + wn + ni * 8 + 2 * gq;
            float2 bb = *(const float2*)(bias + c);
            float v0 = acc[mi][ni][0] + bb.x, v1 = acc[mi][ni][1] + bb.y;
            float v2 = acc[mi][ni][2] + bb.x, v3 = acc[mi][ni][3] + bb.y;
            if (doRelu) {
                v0 = fmaxf(v0, 0.f); v1 = fmaxf(v1, 0.f);
                v2 = fmaxf(v2, 0.f); v3 = fmaxf(v3, 0.f);
            }
            if (resid) {
                float2 r0v = *(const float2*)(resid + (size_t)r * N + c);
                float2 r1v = *(const float2*)(resid + (size_t)(r + 8) * N + c);
                v0 += r0v.x; v1 += r0v.y; v2 += r1v.x; v3 += r1v.y;
            }
            *(float2*)(C + (size_t)r * N + c) = make_float2(v0, v1);
            *(float2*)(C + (size_t)(r + 8) * N + c) = make_float2(v2, v3);
        }
    }
}

// ---------------- attention K/V async loader ----------------
__device__ __forceinline__ void attn_load(const float* __restrict__ kbase,
                                          const float* __restrict__ vbase,
                                          float* sK, float* sV, int tid)
{
    #pragma unroll
    for (int i = 0; i < 4; i++) {
        int idx = tid + i * 128;
        int row = idx >> 3, c4 = (idx & 7) << 2;
        cp16(sK + row * 36 + c4, kbase + (size_t)row * NQKV + c4);
        cp16(sV + row * 36 + c4, vbase + (size_t)row * NQKV + c4);
    }
    CP_COMMIT();
}

// ---------------- tf32 tensor-core flash attention (double-buffered) ----------------
// Block: 64 q-rows x 1 head, 128 threads.
__global__ __launch_bounds__(128)
void attn_tc(const float* __restrict__ qkv, const float* __restrict__ dist,
             const float* __restrict__ tau, float* __restrict__ ctx)
{
    extern __shared__ float sm[];
    float* Qs  = sm;                        // 64*36
    float* KV0 = sm + 64 * 36;              // stage0: K then V
    float* KV1 = KV0 + 2 * 64 * 36;         // stage1
    float* Ps  = KV1 + 2 * 64 * 36;         // 64*68

    int b = blockIdx.z, h = blockIdx.y, i0 = blockIdx.x * 64;
    int tid = threadIdx.x, lane = tid & 31, w = tid >> 5;
    int gr = lane >> 2, gq = lane & 3;
    int lr0 = w * 16 + gr;

    const float sc = 0.17677669529663687f;  // 1/sqrt(32)

    // Q tile: convert + fold scale
    {
        int r0 = tid >> 3, c = (tid & 7) * 4;
        #pragma unroll
        for (int i = 0; i < 4; i++) {
            int row = r0 + 16 * i;
            float4 q = *(const float4*)(qkv + (size_t)(b * NSEQ + i0 + row) * NQKV + h * 32 + c);
            Qs[row * 36 + c]     = __uint_as_float(f2tf(q.x * sc));
            Qs[row * 36 + c + 1] = __uint_as_float(f2tf(q.y * sc));
            Qs[row * 36 + c + 2] = __uint_as_float(f2tf(q.z * sc));
            Qs[row * 36 + c + 3] = __uint_as_float(f2tf(q.w * sc));
        }
    }

    const float* kbase = qkv + (size_t)(b * NSEQ) * NQKV + 256 + h * 32;
    const float* vbase = qkv + (size_t)(b * NSEQ) * NQKV + 512 + h * 32;

    attn_load(kbase, vbase, KV0, KV0 + 64 * 36, tid);

    float tau0 = tau[((size_t)b * NH + h) * NSEQ + i0 + lr0];
    float tau1 = tau[((size_t)b * NH + h) * NSEQ + i0 + lr0 + 8];
    const float* d0p = dist + ((size_t)b * NSEQ + i0 + lr0) * NSEQ;
    const float* d1p = d0p + (size_t)8 * NSEQ;

    float m0 = -1e30f, m1 = -1e30f, l0 = 0.f, l1 = 0.f;
    float o[4][4];
    #pragma unroll
    for (int ni = 0; ni < 4; ni++)
        #pragma unroll
        for (int k = 0; k < 4; k++) o[ni][k] = 0.f;

    for (int jt = 0; jt < NSEQ / 64; jt++) {
        float* cur = (jt & 1) ? KV1 : KV0;
        float* nxt = (jt & 1) ? KV0 : KV1;
        if (jt + 1 < NSEQ / 64) {
            attn_load(kbase + (size_t)(jt + 1) * 64 * NQKV,
                      vbase + (size_t)(jt + 1) * 64 * NQKV,
                      nxt, nxt + 64 * 36, tid);
            asm volatile("cp.async.wait_group 1;");
        } else {
            asm volatile("cp.async.wait_group 0;");
        }
        __syncthreads();
        const float* Ks = cur;
        const float* Vs = cur + 64 * 36;
        int j0 = jt * 64;

        // S = Q @ K^T
        float s[8][4];
        #pragma unroll
        for (int ni = 0; ni < 8; ni++)
            #pragma unroll
            for (int k = 0; k < 4; k++) s[ni][k] = 0.f;

        #pragma unroll
        for (int k0 = 0; k0 < 32; k0 += 8) {
            unsigned af[4];
            af[0] = __float_as_uint(Qs[lr0 * 36 + k0 + gq]);
            af[1] = __float_as_uint(Qs[(lr0 + 8) * 36 + k0 + gq]);
            af[2] = __float_as_uint(Qs[lr0 * 36 + k0 + 4 + gq]);
            af[3] = __float_as_uint(Qs[(lr0 + 8) * 36 + k0 + 4 + gq]);
            #pragma unroll
            for (int ni = 0; ni < 8; ni++) {
                int jj = ni * 8 + gr;
                unsigned b0 = __float_as_uint(Ks[jj * 36 + k0 + gq]);
                unsigned b1 = __float_as_uint(Ks[jj * 36 + k0 + 4 + gq]);
                MMA_TF32(s[ni], af, b0, b1);
            }
        }

        // bias + online softmax
        float tm0 = -1e30f, tm1 = -1e30f;
        #pragma unroll
        for (int ni = 0; ni < 8; ni++) {
            int jc = j0 + ni * 8 + 2 * gq;
            float2 d01 = *(const float2*)(d0p + jc);
            float2 d23 = *(const float2*)(d1p + jc);
            s[ni][0] += d01.x * tau0;
            s[ni][1] += d01.y * tau0;
            s[ni][2] += d23.x * tau1;
            s[ni][3] += d23.y * tau1;
            tm0 = fmaxf(tm0, fmaxf(s[ni][0], s[ni][1]));
            tm1 = fmaxf(tm1, fmaxf(s[ni][2], s[ni][3]));
        }
        tm0 = fmaxf(tm0, __shfl_xor_sync(0xffffffffu, tm0, 1));
        tm0 = fmaxf(tm0, __shfl_xor_sync(0xffffffffu, tm0, 2));
        tm1 = fmaxf(tm1, __shfl_xor_sync(0xffffffffu, tm1, 1));
        tm1 = fmaxf(tm1, __shfl_xor_sync(0xffffffffu, tm1, 2));

        float mn0 = fmaxf(m0, tm0), mn1 = fmaxf(m1, tm1);
        float cor0 = __expf(m0 - mn0), cor1 = __expf(m1 - mn1);
        float ps0 = 0.f, ps1 = 0.f;
        #pragma unroll
        for (int ni = 0; ni < 8; ni++) {
            s[ni][0] = __expf(s[ni][0] - mn0);
            s[ni][1] = __expf(s[ni][1] - mn0);
            s[ni][2] = __expf(s[ni][2] - mn1);
            s[ni][3] = __expf(s[ni][3] - mn1);
            ps0 += s[ni][0] + s[ni][1];
            ps1 += s[ni][2] + s[ni][3];
        }
        ps0 += __shfl_xor_sync(0xffffffffu, ps0, 1);
        ps0 += __shfl_xor_sync(0xffffffffu, ps0, 2);
        ps1 += __shfl_xor_sync(0xffffffffu, ps1, 1);
        ps1 += __shfl_xor_sync(0xffffffffu, ps1, 2);
        l0 = l0 * cor0 + ps0;
        l1 = l1 * cor1 + ps1;
        m0 = mn0; m1 = mn1;

        #pragma unroll
        for (int ni = 0; ni < 4; ni++) {
            o[ni][0] *= cor0; o[ni][1] *= cor0;
            o[ni][2] *= cor1; o[ni][3] *= cor1;
        }

        // stage P (raw float bits, per-warp-private strip)
        #pragma unroll
        for (int ni = 0; ni < 8; ni++) {
            int jc = ni * 8 + 2 * gq;
            Ps[lr0 * 68 + jc]           = s[ni][0];
            Ps[lr0 * 68 + jc + 1]       = s[ni][1];
            Ps[(lr0 + 8) * 68 + jc]     = s[ni][2];
            Ps[(lr0 + 8) * 68 + jc + 1] = s[ni][3];
        }
        __syncwarp();

        // O += P @ V
        #pragma unroll
        for (int k0 = 0; k0 < 64; k0 += 8) {
            unsigned af[4];
            af[0] = __float_as_uint(Ps[lr0 * 68 + k0 + gq]);
            af[1] = __float_as_uint(Ps[(lr0 + 8) * 68 + k0 + gq]);
            af[2] = __float_as_uint(Ps[lr0 * 68 + k0 + 4 + gq]);
            af[3] = __float_as_uint(Ps[(lr0 + 8) * 68 + k0 + 4 + gq]);
            #pragma unroll
            for (int ni = 0; ni < 4; ni++) {
                unsigned b0 = __float_as_uint(Vs[(k0 + gq) * 36 + ni * 8 + gr]);
                unsigned b1 = __float_as_uint(Vs[(k0 + 4 + gq) * 36 + ni * 8 + gr]);
                MMA_TF32(o[ni], af, b0, b1);
            }
        }
        __syncthreads();
    }

    float il0 = 1.f / l0, il1 = 1.f / l1;
    size_t gi0 = (size_t)(b * NSEQ + i0 + lr0) * 256;
    size_t gi1 = gi0 + (size_t)8 * 256;
    #pragma unroll
    for (int ni = 0; ni < 4; ni++) {
        int dcol = h * 32 + ni * 8 + 2 * gq;
        *(float2*)(ctx + gi0 + dcol) = make_float2(o[ni][0] * il0, o[ni][1] * il0);
        *(float2*)(ctx + gi1 + dcol) = make_float2(o[ni][2] * il1, o[ni][3] * il1);
    }
}

// ---------------- row LayerNorm ----------------
__global__ void ln_kernel(const float* __restrict__ in, const float* __restrict__ g,
                          const float* __restrict__ bt, float* __restrict__ out)
{
    int row = blockIdx.x, t = threadIdx.x;
    float v = in[(size_t)row * DM + t];
    float s = v, s2 = v * v;
    #pragma unroll
    for (int o = 16; o > 0; o >>= 1) {
        s  += __shfl_xor_sync(0xffffffffu, s, o);
        s2 += __shfl_xor_sync(0xffffffffu, s2, o);
    }
    __shared__ float rs[8], rs2[8];
    __shared__ float mu_s, rstd_s;
    int w = t >> 5, lane = t & 31;
    if (lane == 0) { rs[w] = s; rs2[w] = s2; }
    __syncthreads();
    if (t == 0) {
        float a = 0.f, b2 = 0.f;
        #pragma unroll
        for (int i = 0; i < 8; i++) { a += rs[i]; b2 += rs2[i]; }
        float mu = a * (1.f / 256.f);
        float var = b2 * (1.f / 256.f) - mu * mu;
        mu_s = mu;
        rstd_s = rsqrtf(var + 1e-5f);
    }
    __syncthreads();
    out[(size_t)row * DM + t] = (v - mu_s) * rstd_s * g[t] + bt[t];
}

// ---------------- launch ----------------
static float* sym_addr(const void* sym)
{
    void* p = nullptr;
    cudaGetSymbolAddress(&p, sym);
    return (float*)p;
}

extern "C" void kernel_launch(void* const* d_in, const int* in_sizes, int n_in,
                              void* d_out, int out_size)
{
    const float* embed = (const float*)d_in[0];
    const float* dist  = (const float*)d_in[2];
    const float* qpos  = (const float*)d_in[3];
    const float* inw   = (const float*)d_in[4];
    const float* inb   = (const float*)d_in[5];
    const float* outw  = (const float*)d_in[6];
    const float* outb  = (const float*)d_in[7];
    const float* tauw  = (const float*)d_in[8];
    const float* taub  = (const float*)d_in[9];
    const float* w1    = (const float*)d_in[10];
    const float* b1    = (const float*)d_in[11];
    const float* w2    = (const float*)d_in[12];
    const float* b2    = (const float*)d_in[13];
    const float* g1    = (const float*)d_in[14];
    const float* be1   = (const float*)d_in[15];
    const float* g2    = (const float*)d_in[16];
    const float* be2   = (const float*)d_in[17];
    float* out = (float*)d_out;

    float* qkin = sym_addr(g_qkin);
    float* qkv  = sym_addr(g_qkv);
    float* tau  = sym_addr(g_tau);
    float* ctx  = sym_addr(g_ctx);
    float* y    = sym_addr(g_y);
    float* x    = sym_addr(g_x);
    float* hbuf = sym_addr(g_h);

    const int smem128 = 2 * (128 + 64) * 36 * 4;   // 55296
    const int smem64  = 2 * (64 + 64) * 36 * 4;    // 36864
    const int smemAtt = (64 * 36 * 5 + 64 * 68) * 4; // 63488

    cudaFuncSetAttribute(gemm_tc<128>, cudaFuncAttributeMaxDynamicSharedMemorySize, smem128);
    cudaFuncSetAttribute(gemm_tc<64>,  cudaFuncAttributeMaxDynamicSharedMemorySize, smem64);
    cudaFuncSetAttribute(attn_tc,      cudaFuncAttributeMaxDynamicSharedMemorySize, smemAtt);

    // 1) qk = embed + query_pos
    add_pos_kernel<<<(MROWS * DM / 4) / 256, 256>>>(
        (const float4*)embed, (const float4*)qpos, (float4*)qkin);

    // 2) tau
    tau_kernel<<<512, 256>>>(embed, tauw, taub, tau);

    // 3) fused QKV projection: [4096,768]; A = qkin for n<512, embed for n>=512
    gemm_tc<128><<<dim3(NQKV / 64, MROWS / 128), 256, smem128>>>(
        qkin, embed, inw, inb, nullptr, qkv, MROWS, NQKV, DM, 0, 512);

    // 4) attention
    attn_tc<<<dim3(NSEQ / 64, NH, BD), 128, smemAtt>>>(qkv, dist, tau, ctx);

    // 5) out projection + residual(embed)
    gemm_tc<64><<<dim3(DM / 64, MROWS / 64), 128, smem64>>>(
        ctx, ctx, outw, outb, embed, y, MROWS, DM, DM, 0, 1 << 30);

    // 6) LN1
    ln_kernel<<<MROWS, 256>>>(y, g1, be1, x);

    // 7) FFN1 + ReLU
    gemm_tc<128><<<dim3(DFFN / 64, MROWS / 128), 256, smem128>>>(
        x, x, w1, b1, nullptr, hbuf, MROWS, DFFN, DM, 1, 1 << 30);

    // 8) FFN2 + residual(x)
    gemm_tc<64><<<dim3(DM / 64, MROWS / 64), 128, smem64>>>(
        hbuf, hbuf, w2, b2, x, y, MROWS, DM, DFFN, 0, 1 << 30);

    // 9) LN2 -> out
    ln_kernel<<<MROWS, 256>>>(y, g2, be2, out);
}